// round 12
// baseline (speedup 1.0000x reference)
#include <cuda_runtime.h>
#include <cuda_bf16.h>
#include <cstdint>
#include <cstring>

// Problem constants
#define T_ROWS   8192
#define KDIM     4096
#define NI       63
#define NPAD     64
#define NLEAF    64
#define NCLS     10

// Tiling: BM=16, BK=64; grid=512 -> 3 CTAs/SM. 8 warps = (ks 0..3 k16-slice)
// x (nh 0..1 n32-half). A smem reads dup x2, B reads dedup.
#define BM       16
#define BK       64
#define NKT      (KDIM / BK)       // 64 k-tiles
#define THREADS  256
#define STAGES   5                 // 5 buffers, 4 groups in flight

#define XSTRIDE   72               // fp32 words per X smem row (288B; conflict-free LDS.64)
#define XSTG_WORDS (BM * XSTRIDE)  // 1152 words = 4608 B
#define WSTG_BYTES (NPAD * 128)    // 8192 B (64 rows x 128B, XOR-swizzled 16B granules)
#define STG_BYTES  (XSTG_WORDS * 4 + WSTG_BYTES)   // 12800
#define DYN_SMEM   (STAGES * STG_BYTES)            // 64000 B -> 3 CTAs/SM

#define CB_STRIDE  34              // combine buffer row stride (words)

// Scratch (allocation-free rule: __device__ globals)
__device__ __nv_bfloat16 g_Wbf[NPAD * KDIM];
__device__ float         g_leaf_r[NLEAF];

// ---------------------------------------------------------------------------
// Prep: W -> bf16 (padded to 64 rows), leaf_r, zero output scalar.
// 64 CTAs x 256 thr, 4 independent float4s per thread (MLP=4).
// ---------------------------------------------------------------------------
__global__ void prep_kernel(const float* __restrict__ W,
                            const float* __restrict__ leaf_dist,
                            const float* __restrict__ class_reward,
                            float* __restrict__ out) {
    int t0 = blockIdx.x * 256 + threadIdx.x;
    float4 v[4];
    int    bases[4];
    #pragma unroll
    for (int i = 0; i < 4; ++i) {
        int idx4 = t0 + i * 16384;          // 0..65535
        int base = idx4 * 4;
        bases[i] = base;
        int n = base >> 12;                 // /KDIM
        v[i] = (n < NI) ? *reinterpret_cast<const float4*>(W + base)
                        : make_float4(0.f, 0.f, 0.f, 0.f);
    }
    #pragma unroll
    for (int i = 0; i < 4; ++i) {
        __nv_bfloat162 lo = __floats2bfloat162_rn(v[i].x, v[i].y);
        __nv_bfloat162 hi = __floats2bfloat162_rn(v[i].z, v[i].w);
        uint32_t ulo, uhi;
        memcpy(&ulo, &lo, 4);
        memcpy(&uhi, &hi, 4);
        *reinterpret_cast<uint2*>(g_Wbf + bases[i]) = make_uint2(ulo, uhi);
    }
    if (blockIdx.x == 0) {
        int t = threadIdx.x;
        if (t < NLEAF) {
            const float* ld = leaf_dist + t * NCLS;
            float mx = ld[0];
            #pragma unroll
            for (int c = 1; c < NCLS; ++c) mx = fmaxf(mx, ld[c]);
            float s = 0.f, r = 0.f;
            #pragma unroll
            for (int c = 0; c < NCLS; ++c) {
                float e = __expf(ld[c] - mx);
                s += e;
                r += e * class_reward[c];
            }
            g_leaf_r[t] = r / s;
        }
        if (t == 0) out[0] = 0.f;
    }
}

// ---------------------------------------------------------------------------
// Helpers
// ---------------------------------------------------------------------------
__device__ __forceinline__ uint32_t smem_u32(const void* p) {
    return (uint32_t)__cvta_generic_to_shared(p);
}
__device__ __forceinline__ void cp16(void* dst, const void* src) {
    uint32_t d = smem_u32(dst);
    asm volatile("cp.async.cg.shared.global [%0], [%1], 16;\n" :: "r"(d), "l"(src));
}
__device__ __forceinline__ uint32_t pack_bf16(float x, float y) {
    __nv_bfloat162 h = __floats2bfloat162_rn(x, y);
    uint32_t u;
    memcpy(&u, &h, 4);
    return u;
}

// ---------------------------------------------------------------------------
// Main: BM=16/BK=64, grid=512, 8 warps (ks x nh), 3 CTAs/SM, 5-stage
// cp.async pipeline; k-partials combined in smem; fused sigmoid + tree.
// ---------------------------------------------------------------------------
__global__ __launch_bounds__(THREADS, 3)
void sdt_main(const float* __restrict__ X,
              const float* __restrict__ b,
              const float* __restrict__ beta,
              float* __restrict__ out) {
    extern __shared__ __align__(16) unsigned char dynsm[];
    float*         Xs  = reinterpret_cast<float*>(dynsm);
    unsigned char* Wsb = dynsm + STAGES * XSTG_WORDS * 4;
    float*         Cb  = reinterpret_cast<float*>(dynsm);   // combine: [8][16][CB_STRIDE]
    float*         Ps  = reinterpret_cast<float*>(dynsm);   // final P, stride 65 (after combine)

    __shared__ float s_b[NPAD], s_beta[NPAD];

    const int tid  = threadIdx.x;
    const int lane = tid & 31;
    const int warp = tid >> 5;        // 0..7
    const int ks   = warp >> 1;       // 0..3 : k16 slice in tile
    const int nh   = warp & 1;        // 0..1 : n32 half
    const int m0   = blockIdx.x * BM;

    if (tid < NPAD) {
        s_b[tid]    = (tid < NI) ? b[tid]    : 0.f;
        s_beta[tid] = (tid < NI) ? beta[tid] : 0.f;
    }

    const float* Xg = X + (size_t)m0 * KDIM;

    // ---- stage issue: X 1 x 16B + W 2 x 16B per thread ----
    auto issue_stage = [&](int kt) {
        if (kt < NKT) {
            unsigned char* xb = dynsm + (kt % STAGES) * XSTG_WORDS * 4;
            const float*   xs = Xg + kt * BK;
            {
                int row = tid >> 4;          // 0..15
                int gr  = tid & 15;          // 16B granule
                cp16(xb + row * (XSTRIDE * 4) + gr * 16, xs + row * KDIM + gr * 4);
            }
            unsigned char* wb = Wsb + (kt % STAGES) * WSTG_BYTES;
            const __nv_bfloat16* ws = g_Wbf + kt * BK;
            #pragma unroll
            for (int i = 0; i < 2; ++i) {
                int c   = tid + i * 256;     // 0..511
                int row = c >> 3;            // 0..63
                int gr  = c & 7;             // 8 granules per 128B row
                cp16(wb + row * 128 + ((gr ^ (row & 7)) * 16), ws + row * KDIM + gr * 8);
            }
        }
        asm volatile("cp.async.commit_group;\n" ::: "memory");
    };

    // prologue: 4 stages in flight
    issue_stage(0);
    issue_stage(1);
    issue_stage(2);
    issue_stage(3);

    float acc[4][4];   // [n8 tile within n32][frag]
    #pragma unroll
    for (int n = 0; n < 4; ++n)
        #pragma unroll
        for (int c = 0; c < 4; ++c) acc[n][c] = 0.f;

    // lane geometry
    const int aq    = lane >> 2;            // A row-in-8
    const int at2   = (lane & 3) * 2;       // A k pair
    const int akoff = ks * 16 + at2;        // word offset of this warp's k-slice
    const int brow  = nh * 32 + ((lane & 16) >> 1) + (lane & 7);   // + nt2*16
    const int bgr   = ks * 2 + ((lane & 8) >> 3);                  // W granule 0..7

    for (int kt = 0; kt < NKT; ++kt) {
        asm volatile("cp.async.wait_group 3;\n" ::: "memory");  // stage kt ready
        __syncthreads();                                        // oldest buffer free
        issue_stage(kt + 4);

        const float*         xb = Xs + (kt % STAGES) * XSTG_WORDS;
        const unsigned char* wb = Wsb + (kt % STAGES) * WSTG_BYTES;

        // A fragment (16 rows) for this warp's k-slice
        const float* pr = xb + aq * XSTRIDE + akoff;
        float2 v00 = *reinterpret_cast<const float2*>(pr);
        float2 v10 = *reinterpret_cast<const float2*>(pr + 8 * XSTRIDE);
        float2 v01 = *reinterpret_cast<const float2*>(pr + 8);
        float2 v11 = *reinterpret_cast<const float2*>(pr + 8 * XSTRIDE + 8);
        uint32_t a0 = pack_bf16(v00.x, v00.y);
        uint32_t a1 = pack_bf16(v10.x, v10.y);
        uint32_t a2 = pack_bf16(v01.x, v01.y);
        uint32_t a3 = pack_bf16(v11.x, v11.y);

        // B fragments: 2 x ldmatrix.x4 covering this warp's n32 at its k16
        uint32_t bb[2][4];
        #pragma unroll
        for (int nt2 = 0; nt2 < 2; ++nt2) {
            int      row   = nt2 * 16 + brow;
            uint32_t baddr = smem_u32(wb + row * 128 + ((bgr ^ (row & 7)) * 16));
            asm volatile("ldmatrix.sync.aligned.m8n8.x4.shared.b16 {%0,%1,%2,%3}, [%4];\n"
                         : "=r"(bb[nt2][0]), "=r"(bb[nt2][1]), "=r"(bb[nt2][2]), "=r"(bb[nt2][3])
                         : "r"(baddr));
        }

        // 4 MMAs: 4 n-tiles
        #pragma unroll
        for (int nt2 = 0; nt2 < 2; ++nt2) {
            #pragma unroll
            for (int pn = 0; pn < 2; ++pn) {
                const int n = nt2 * 2 + pn;
                asm volatile(
                    "mma.sync.aligned.m16n8k16.row.col.f32.bf16.bf16.f32 "
                    "{%0,%1,%2,%3}, {%4,%5,%6,%7}, {%8,%9}, {%0,%1,%2,%3};\n"
                    : "+f"(acc[n][0]), "+f"(acc[n][1]), "+f"(acc[n][2]), "+f"(acc[n][3])
                    : "r"(a0), "r"(a1), "r"(a2), "r"(a3),
                      "r"(bb[nt2][pn * 2]), "r"(bb[nt2][pn * 2 + 1]));
            }
        }
    }

    asm volatile("cp.async.wait_group 0;\n" ::: "memory");
    __syncthreads();

    // --- combine: each warp stores its 16x32 k-partial ---
    {
        float* wbuf = Cb + warp * (16 * CB_STRIDE);
        #pragma unroll
        for (int n = 0; n < 4; ++n) {
            const int col = n * 8 + (lane & 3) * 2;    // 0..30 local
            const int r0  = lane >> 2;
            *reinterpret_cast<float2*>(wbuf + r0 * CB_STRIDE + col) =
                make_float2(acc[n][0], acc[n][1]);
            *reinterpret_cast<float2*>(wbuf + (r0 + 8) * CB_STRIDE + col) =
                make_float2(acc[n][2], acc[n][3]);
        }
    }
    __syncthreads();

    // --- reduce 4 k-partials per n-half, sigmoid, write P (aliases Cb) ---
    float2 zred[2];
    #pragma unroll
    for (int i = 0; i < 2; ++i) {
        int pi  = tid + i * 256;        // 0..511 pair index
        int row = pi >> 5;              // 0..15
        int col = (pi & 31) * 2;        // 0..62 global col
        int nhh = col >> 5;             // n-half
        int cl  = col & 31;             // local col
        float2 zv = make_float2(0.f, 0.f);
        #pragma unroll
        for (int w = 0; w < 4; ++w) {
            float2 p = *reinterpret_cast<const float2*>(
                Cb + (w * 2 + nhh) * (16 * CB_STRIDE) + row * CB_STRIDE + cl);
            zv.x += p.x;
            zv.y += p.y;
        }
        zred[i] = zv;
    }
    __syncthreads();
    #pragma unroll
    for (int i = 0; i < 2; ++i) {
        int pi  = tid + i * 256;
        int row = pi >> 5;
        int col = (pi & 31) * 2;
        #pragma unroll
        for (int j = 0; j < 2; ++j) {
            int n = col + j;
            if (n < NI) {
                float z = (j ? zred[i].y : zred[i].x);
                float u = s_beta[n] * (z + s_b[n]);
                Ps[row * (NPAD + 1) + n] = 1.f / (1.f + __expf(-u));
            }
        }
    }
    __syncthreads();

    // --- tree walk: 8 warps x 2 rows; lane handles leaves (lane, lane+32) ---
    const float lr0 = g_leaf_r[lane];
    const float lr1 = g_leaf_r[lane + 32];
    float wsum = 0.f;
    #pragma unroll
    for (int r = 0; r < 2; ++r) {
        const int row = warp * 2 + r;
        const float* Pr = Ps + row * (NPAD + 1);
        float v0 = 1.f, v1 = 1.f;
        const int L0 = lane, L1 = lane + 32;
        #pragma unroll
        for (int k = 0; k < 6; ++k) {
            const int off = (1 << k) - 1;
            const float P0 = Pr[off + (L0 >> (6 - k))];
            const float P1 = Pr[off + (L1 >> (6 - k))];
            v0 *= ((L0 >> (5 - k)) & 1) ? (1.f - P0) : P0;
            v1 *= ((L1 >> (5 - k)) & 1) ? (1.f - P1) : P1;
        }
        wsum += v0 * lr0 + v1 * lr1;
    }
    #pragma unroll
    for (int s = 16; s > 0; s >>= 1)
        wsum += __shfl_down_sync(0xffffffffu, wsum, s);
    if (lane == 0) atomicAdd(out, wsum);
}

// ---------------------------------------------------------------------------
// kernel_launch
// ---------------------------------------------------------------------------
extern "C" void kernel_launch(void* const* d_in, const int* in_sizes, int n_in,
                              void* d_out, int out_size) {
    const float* X    = (const float*)d_in[0];
    const float* W    = (const float*)d_in[1];
    const float* b    = (const float*)d_in[2];
    const float* beta = (const float*)d_in[3];
    const float* leaf = (const float*)d_in[4];
    const float* cls  = (const float*)d_in[5];
    float* out = (float*)d_out;

    cudaFuncSetAttribute(sdt_main, cudaFuncAttributeMaxDynamicSharedMemorySize, DYN_SMEM);

    prep_kernel<<<64, 256>>>(W, leaf, cls, out);
    sdt_main<<<T_ROWS / BM, THREADS, DYN_SMEM>>>(X, b, beta, out);
}

// round 13
// speedup vs baseline: 1.3364x; 1.3364x over previous
#include <cuda_runtime.h>
#include <cuda_bf16.h>
#include <cstdint>
#include <cstring>

// Problem constants
#define T_ROWS   8192
#define KDIM     4096
#define NI       63
#define NPAD     64
#define NLEAF    64
#define NCLS     10

// Tiling: BM=32, BK=64; 8 warps = (ks 0..3 k16-slice) x (nh 0..1 n32-half).
// Cross-tile register double-buffered fragments: MMA(kt) overlaps loads(kt+1).
#define BM       32
#define BK       64
#define NKT      (KDIM / BK)       // 64 k-tiles
#define THREADS  256
#define STAGES   6                 // 6 buffers, 5 groups in flight

#define XSTRIDE   72               // fp32 words per X smem row (288B; conflict-free LDS.64)
#define XSTG_WORDS (BM * XSTRIDE)  // 2304 words = 9216 B
#define WSTG_BYTES (NPAD * 128)    // 8192 B (64 rows x 128B, XOR-swizzled 16B granules)
#define STG_BYTES  (XSTG_WORDS * 4 + WSTG_BYTES)   // 17408
#define DYN_SMEM   (STAGES * STG_BYTES)            // 104448 B -> 2 CTAs/SM

#define CB_STRIDE  34              // combine buffer row stride (words)

// Scratch (allocation-free rule: __device__ globals)
__device__ __nv_bfloat16 g_Wbf[NPAD * KDIM];
__device__ float         g_leaf_r[NLEAF];

// ---------------------------------------------------------------------------
// Prep: W -> bf16 (padded to 64 rows), leaf_r, zero output scalar.
// ---------------------------------------------------------------------------
__global__ void prep_kernel(const float* __restrict__ W,
                            const float* __restrict__ leaf_dist,
                            const float* __restrict__ class_reward,
                            float* __restrict__ out) {
    int t0 = blockIdx.x * 256 + threadIdx.x;
    float4 v[4];
    int    bases[4];
    #pragma unroll
    for (int i = 0; i < 4; ++i) {
        int idx4 = t0 + i * 16384;          // 0..65535
        int base = idx4 * 4;
        bases[i] = base;
        int n = base >> 12;                 // /KDIM
        v[i] = (n < NI) ? *reinterpret_cast<const float4*>(W + base)
                        : make_float4(0.f, 0.f, 0.f, 0.f);
    }
    #pragma unroll
    for (int i = 0; i < 4; ++i) {
        __nv_bfloat162 lo = __floats2bfloat162_rn(v[i].x, v[i].y);
        __nv_bfloat162 hi = __floats2bfloat162_rn(v[i].z, v[i].w);
        uint32_t ulo, uhi;
        memcpy(&ulo, &lo, 4);
        memcpy(&uhi, &hi, 4);
        *reinterpret_cast<uint2*>(g_Wbf + bases[i]) = make_uint2(ulo, uhi);
    }
    if (blockIdx.x == 0) {
        int t = threadIdx.x;
        if (t < NLEAF) {
            const float* ld = leaf_dist + t * NCLS;
            float mx = ld[0];
            #pragma unroll
            for (int c = 1; c < NCLS; ++c) mx = fmaxf(mx, ld[c]);
            float s = 0.f, r = 0.f;
            #pragma unroll
            for (int c = 0; c < NCLS; ++c) {
                float e = __expf(ld[c] - mx);
                s += e;
                r += e * class_reward[c];
            }
            g_leaf_r[t] = r / s;
        }
        if (t == 0) out[0] = 0.f;
    }
}

// ---------------------------------------------------------------------------
// Helpers
// ---------------------------------------------------------------------------
__device__ __forceinline__ uint32_t smem_u32(const void* p) {
    return (uint32_t)__cvta_generic_to_shared(p);
}
__device__ __forceinline__ void cp16(void* dst, const void* src) {
    uint32_t d = smem_u32(dst);
    asm volatile("cp.async.cg.shared.global [%0], [%1], 16;\n" :: "r"(d), "l"(src));
}
__device__ __forceinline__ uint32_t pack_bf16(float x, float y) {
    __nv_bfloat162 h = __floats2bfloat162_rn(x, y);
    uint32_t u;
    memcpy(&u, &h, 4);
    return u;
}

// per-warp per-tile fragments: A (2 slabs x 4) + B (2 n8-pairs x 4)
struct Frag {
    uint32_t a[2][4];
    uint32_t b[2][4];
};

// ---------------------------------------------------------------------------
// Main: BM=32/BK=64, 8 warps (ks x nh), 2 CTAs/SM, 6-stage cp.async pipeline,
// cross-tile register double-buffered fragments; fused sigmoid + tree.
// ---------------------------------------------------------------------------
__global__ __launch_bounds__(THREADS, 2)
void sdt_main(const float* __restrict__ X,
              const float* __restrict__ b,
              const float* __restrict__ beta,
              float* __restrict__ out) {
    extern __shared__ __align__(16) unsigned char dynsm[];
    float*         Xs  = reinterpret_cast<float*>(dynsm);
    unsigned char* Wsb = dynsm + STAGES * XSTG_WORDS * 4;
    float*         Cb  = reinterpret_cast<float*>(dynsm);   // combine: [8][32][CB_STRIDE]
    float*         Ps  = reinterpret_cast<float*>(dynsm);   // final P, stride 65 (after combine)

    __shared__ float s_b[NPAD], s_beta[NPAD];

    const int tid  = threadIdx.x;
    const int lane = tid & 31;
    const int warp = tid >> 5;        // 0..7
    const int ks   = warp >> 1;       // 0..3 : k16 slice in tile
    const int nh   = warp & 1;        // 0..1 : n32 half
    const int m0   = blockIdx.x * BM;

    if (tid < NPAD) {
        s_b[tid]    = (tid < NI) ? b[tid]    : 0.f;
        s_beta[tid] = (tid < NI) ? beta[tid] : 0.f;
    }

    const float* Xg = X + (size_t)m0 * KDIM;

    // ---- stage issue: X 2 x 16B + W 2 x 16B per thread ----
    auto issue_stage = [&](int kt) {
        if (kt < NKT) {
            unsigned char* xb = dynsm + (kt % STAGES) * XSTG_WORDS * 4;
            const float*   xs = Xg + kt * BK;
            #pragma unroll
            for (int i = 0; i < 2; ++i) {
                int c   = tid + i * 256;     // 0..511
                int row = c >> 4;            // 0..31
                int gr  = c & 15;            // 16B granule
                cp16(xb + row * (XSTRIDE * 4) + gr * 16, xs + row * KDIM + gr * 4);
            }
            unsigned char* wb = Wsb + (kt % STAGES) * WSTG_BYTES;
            const __nv_bfloat16* ws = g_Wbf + kt * BK;
            #pragma unroll
            for (int i = 0; i < 2; ++i) {
                int c   = tid + i * 256;     // 0..511
                int row = c >> 3;            // 0..63
                int gr  = c & 7;             // 8 granules per 128B row
                cp16(wb + row * 128 + ((gr ^ (row & 7)) * 16), ws + row * KDIM + gr * 8);
            }
        }
        asm volatile("cp.async.commit_group;\n" ::: "memory");
    };

    // lane geometry
    const int aq    = lane >> 2;            // A row-in-8
    const int at2   = (lane & 3) * 2;       // A k pair
    const int akoff = ks * 16 + at2;        // word offset of this warp's k-slice
    const int brow  = nh * 32 + ((lane & 16) >> 1) + (lane & 7);   // + nt2*16
    const int bgr   = ks * 2 + ((lane & 8) >> 3);                  // W granule 0..7

    // load per-warp fragments for tile kt from its stage buffer
    auto load_frag = [&](Frag& f, int kt) {
        const float*         xb = Xs + (kt % STAGES) * XSTG_WORDS;
        const unsigned char* wb = Wsb + (kt % STAGES) * WSTG_BYTES;
        #pragma unroll
        for (int s = 0; s < 2; ++s) {
            const float* pr = xb + (s * 16 + aq) * XSTRIDE + akoff;
            float2 v00 = *reinterpret_cast<const float2*>(pr);
            float2 v10 = *reinterpret_cast<const float2*>(pr + 8 * XSTRIDE);
            float2 v01 = *reinterpret_cast<const float2*>(pr + 8);
            float2 v11 = *reinterpret_cast<const float2*>(pr + 8 * XSTRIDE + 8);
            f.a[s][0] = pack_bf16(v00.x, v00.y);
            f.a[s][1] = pack_bf16(v10.x, v10.y);
            f.a[s][2] = pack_bf16(v01.x, v01.y);
            f.a[s][3] = pack_bf16(v11.x, v11.y);
        }
        #pragma unroll
        for (int nt2 = 0; nt2 < 2; ++nt2) {
            int      row   = nt2 * 16 + brow;
            uint32_t baddr = smem_u32(wb + row * 128 + ((bgr ^ (row & 7)) * 16));
            asm volatile("ldmatrix.sync.aligned.m8n8.x4.shared.b16 {%0,%1,%2,%3}, [%4];\n"
                         : "=r"(f.b[nt2][0]), "=r"(f.b[nt2][1]),
                           "=r"(f.b[nt2][2]), "=r"(f.b[nt2][3])
                         : "r"(baddr));
        }
    };

    float acc[2][4][4];   // [m16 slab][n8 tile within n32][frag]
    #pragma unroll
    for (int s = 0; s < 2; ++s)
        #pragma unroll
        for (int n = 0; n < 4; ++n)
            #pragma unroll
            for (int c = 0; c < 4; ++c) acc[s][n][c] = 0.f;

    auto do_mma = [&](const Frag& f) {
        #pragma unroll
        for (int nt2 = 0; nt2 < 2; ++nt2) {
            #pragma unroll
            for (int pn = 0; pn < 2; ++pn) {
                const int n = nt2 * 2 + pn;
                #pragma unroll
                for (int s = 0; s < 2; ++s) {
                    asm volatile(
                        "mma.sync.aligned.m16n8k16.row.col.f32.bf16.bf16.f32 "
                        "{%0,%1,%2,%3}, {%4,%5,%6,%7}, {%8,%9}, {%0,%1,%2,%3};\n"
                        : "+f"(acc[s][n][0]), "+f"(acc[s][n][1]),
                          "+f"(acc[s][n][2]), "+f"(acc[s][n][3])
                        : "r"(f.a[s][0]), "r"(f.a[s][1]), "r"(f.a[s][2]), "r"(f.a[s][3]),
                          "r"(f.b[nt2][pn * 2]), "r"(f.b[nt2][pn * 2 + 1]));
                }
            }
        }
    };

    // prologue: 5 stages in flight, then load frags for tile 0
    issue_stage(0);
    issue_stage(1);
    issue_stage(2);
    issue_stage(3);
    issue_stage(4);
    asm volatile("cp.async.wait_group 4;\n" ::: "memory");   // stage 0 ready
    Frag f0, f1;
    load_frag(f0, 0);

    // main loop, unrolled x2 for register ping-pong.
    // Body(kt, fc, fn): MMA(fc); sync(recycle buffer kt-1); issue(kt+5);
    //                   wait(stage kt+1); load fn <- kt+1.
    #pragma unroll 1
    for (int kt = 0; kt < NKT; kt += 2) {
        // tile kt (even) uses f0
        do_mma(f0);
        __syncthreads();
        issue_stage(kt + 5);
        asm volatile("cp.async.wait_group 4;\n" ::: "memory");
        load_frag(f1, kt + 1);

        // tile kt+1 (odd) uses f1
        do_mma(f1);
        __syncthreads();
        issue_stage(kt + 6);
        asm volatile("cp.async.wait_group 4;\n" ::: "memory");
        if (kt + 2 < NKT) load_frag(f0, kt + 2);
    }

    asm volatile("cp.async.wait_group 0;\n" ::: "memory");
    __syncthreads();

    // --- combine: each warp stores its 32x32 k-partial ---
    {
        float* wbuf = Cb + warp * (32 * CB_STRIDE);
        #pragma unroll
        for (int s = 0; s < 2; ++s) {
            #pragma unroll
            for (int n = 0; n < 4; ++n) {
                const int col = n * 8 + (lane & 3) * 2;    // 0..30 local
                const int r0  = s * 16 + (lane >> 2);
                *reinterpret_cast<float2*>(wbuf + r0 * CB_STRIDE + col) =
                    make_float2(acc[s][n][0], acc[s][n][1]);
                *reinterpret_cast<float2*>(wbuf + (r0 + 8) * CB_STRIDE + col) =
                    make_float2(acc[s][n][2], acc[s][n][3]);
            }
        }
    }
    __syncthreads();

    // --- reduce 4 k-partials per n-half, sigmoid, write P (aliases Cb) ---
    float2 zred[4];
    #pragma unroll
    for (int i = 0; i < 4; ++i) {
        int pi  = tid + i * 256;        // 0..1023 pair index
        int row = pi >> 5;              // 0..31
        int col = (pi & 31) * 2;        // 0..62 global col
        int nhh = col >> 5;             // n-half
        int cl  = col & 31;             // local col
        float2 zv = make_float2(0.f, 0.f);
        #pragma unroll
        for (int w = 0; w < 4; ++w) {
            float2 p = *reinterpret_cast<const float2*>(
                Cb + (w * 2 + nhh) * (32 * CB_STRIDE) + row * CB_STRIDE + cl);
            zv.x += p.x;
            zv.y += p.y;
        }
        zred[i] = zv;
    }
    __syncthreads();
    #pragma unroll
    for (int i = 0; i < 4; ++i) {
        int pi  = tid + i * 256;
        int row = pi >> 5;
        int col = (pi & 31) * 2;
        #pragma unroll
        for (int j = 0; j < 2; ++j) {
            int n = col + j;
            if (n < NI) {
                float z = (j ? zred[i].y : zred[i].x);
                float u = s_beta[n] * (z + s_b[n]);
                Ps[row * (NPAD + 1) + n] = 1.f / (1.f + __expf(-u));
            }
        }
    }
    __syncthreads();

    // --- tree walk: 8 warps x 4 rows; lane handles leaves (lane, lane+32) ---
    const float lr0 = g_leaf_r[lane];
    const float lr1 = g_leaf_r[lane + 32];
    float wsum = 0.f;
    #pragma unroll
    for (int r = 0; r < 4; ++r) {
        const int row = warp * 4 + r;
        const float* Pr = Ps + row * (NPAD + 1);
        float v0 = 1.f, v1 = 1.f;
        const int L0 = lane, L1 = lane + 32;
        #pragma unroll
        for (int k = 0; k < 6; ++k) {
            const int off = (1 << k) - 1;
            const float P0 = Pr[off + (L0 >> (6 - k))];
            const float P1 = Pr[off + (L1 >> (6 - k))];
            v0 *= ((L0 >> (5 - k)) & 1) ? (1.f - P0) : P0;
            v1 *= ((L1 >> (5 - k)) & 1) ? (1.f - P1) : P1;
        }
        wsum += v0 * lr0 + v1 * lr1;
    }
    #pragma unroll
    for (int s = 16; s > 0; s >>= 1)
        wsum += __shfl_down_sync(0xffffffffu, wsum, s);
    if (lane == 0) atomicAdd(out, wsum);
}

// ---------------------------------------------------------------------------
// kernel_launch
// ---------------------------------------------------------------------------
extern "C" void kernel_launch(void* const* d_in, const int* in_sizes, int n_in,
                              void* d_out, int out_size) {
    const float* X    = (const float*)d_in[0];
    const float* W    = (const float*)d_in[1];
    const float* b    = (const float*)d_in[2];
    const float* beta = (const float*)d_in[3];
    const float* leaf = (const float*)d_in[4];
    const float* cls  = (const float*)d_in[5];
    float* out = (float*)d_out;

    cudaFuncSetAttribute(sdt_main, cudaFuncAttributeMaxDynamicSharedMemorySize, DYN_SMEM);

    prep_kernel<<<64, 256>>>(W, leaf, cls, out);
    sdt_main<<<T_ROWS / BM, THREADS, DYN_SMEM>>>(X, b, beta, out);
}